// round 6
// baseline (speedup 1.0000x reference)
#include <cuda_runtime.h>

#define NBLOCKS 1184
#define NTHREADS 256

__device__ float        g_partials[NBLOCKS];
__device__ unsigned int g_counter = 0;   // self-resetting via atomicInc wrap

__global__ __launch_bounds__(NTHREADS, 8)
void qsum_fused_kernel(const float* __restrict__ phi,
                       const float* __restrict__ w,
                       int n4, int n_total, int chunk,
                       float bias, float inv_N,
                       float* __restrict__ out) {
    const float4* __restrict__ p4 = reinterpret_cast<const float4*>(phi);
    const float4* __restrict__ w4 = reinterpret_cast<const float4*>(w);

    float acc = 0.0f;

    // Block-contiguous tiling: CTA b owns float4 indices [b*chunk, (b+1)*chunk).
    // Each iteration the CTA reads a dense 4KB line per array; consecutive
    // iterations advance sequentially through the slab (max open-row locality).
    const int beg = blockIdx.x * chunk;
    int end = beg + chunk;
    if (end > n4) end = n4;

    for (int i = beg + threadIdx.x; i < end; i += NTHREADS) {
        float4 a = __ldcs(p4 + i);
        float4 b = __ldcs(w4 + i);
        acc += __cosf(a.x * b.x);
        acc += __cosf(a.y * b.y);
        acc += __cosf(a.z * b.z);
        acc += __cosf(a.w * b.w);
    }

    // Scalar tail (n_total not multiple of 4) — handled by CTA 0
    if (blockIdx.x == 0) {
        int ti = n4 * 4 + threadIdx.x;
        if (ti < n_total) {
            acc += __cosf(phi[ti] * w[ti]);
        }
    }

    // Warp reduce
    #pragma unroll
    for (int o = 16; o > 0; o >>= 1)
        acc += __shfl_xor_sync(0xffffffffu, acc, o);

    __shared__ float smem[NTHREADS / 32];
    if ((threadIdx.x & 31) == 0)
        smem[threadIdx.x >> 5] = acc;
    __syncthreads();

    // Block partial -> global, then last block finishes
    __shared__ bool s_is_last;
    if (threadIdx.x == 0) {
        float v = 0.0f;
        #pragma unroll
        for (int k = 0; k < NTHREADS / 32; k++)
            v += smem[k];
        g_partials[blockIdx.x] = v;
        __threadfence();
        unsigned int ticket = atomicInc(&g_counter, NBLOCKS - 1);
        s_is_last = (ticket == NBLOCKS - 1);
    }
    __syncthreads();

    if (s_is_last) {
        // Deterministic final reduction: fixed strided assignment + fixed tree
        float v = 0.0f;
        for (int k = threadIdx.x; k < NBLOCKS; k += NTHREADS)
            v += g_partials[k];

        #pragma unroll
        for (int o = 16; o > 0; o >>= 1)
            v += __shfl_xor_sync(0xffffffffu, v, o);

        if ((threadIdx.x & 31) == 0)
            smem[threadIdx.x >> 5] = v;
        __syncthreads();

        if (threadIdx.x < 32) {
            float t = (threadIdx.x < NTHREADS / 32) ? smem[threadIdx.x] : 0.0f;
            #pragma unroll
            for (int o = 4; o > 0; o >>= 1)
                t += __shfl_xor_sync(0xffffffffu, t, o);
            if (threadIdx.x == 0)
                out[0] = (t + bias) * inv_N;
        }
    }
}

extern "C" void kernel_launch(void* const* d_in, const int* in_sizes, int n_in,
                              void* d_out, int out_size) {
    const float* phi = (const float*)d_in[0];
    const float* w   = (const float*)d_in[1];

    long long C = (long long)in_sizes[0];

    // N = 2^ceil(log2(C))
    int n = 0;
    while ((1LL << n) < C) n++;
    long long N = 1LL << n;

    float bias  = (float)(double)(N - C);
    float inv_N = (float)(1.0 / (double)N);

    int n4 = (int)(C / 4);
    int chunk = (n4 + NBLOCKS - 1) / NBLOCKS;   // float4 elems per CTA

    qsum_fused_kernel<<<NBLOCKS, NTHREADS>>>(phi, w, n4, (int)C, chunk,
                                             bias, inv_N, (float*)d_out);
}

// round 7
// speedup vs baseline: 1.0499x; 1.0499x over previous
#include <cuda_runtime.h>

#define NBLOCKS 1184
#define NTHREADS 256

__device__ float        g_partials[NBLOCKS];
__device__ unsigned int g_counter = 0;   // self-resetting via atomicInc wrap

__global__ __launch_bounds__(NTHREADS, 8)
void qsum_fused_kernel(const float* __restrict__ phi,
                       const float* __restrict__ w,
                       long long n4, long long n_total,
                       float bias, float inv_N,
                       float* __restrict__ out) {
    const float4* __restrict__ p4 = reinterpret_cast<const float4*>(phi);
    const float4* __restrict__ w4 = reinterpret_cast<const float4*>(w);

    float acc = 0.0f;
    long long tid    = (long long)blockIdx.x * NTHREADS + threadIdx.x;
    long long stride = (long long)gridDim.x * NTHREADS;

    // Grid-stride loop: 2x LDG.128 per iter. Empirically the best DRAM/LTS
    // pattern on this part (beats strided unroll, SW pipelining, and
    // block-contiguous tiling). Runs at the LTS service-rate ceiling.
    for (long long i = tid; i < n4; i += stride) {
        float4 a = p4[i];
        float4 b = w4[i];
        acc += __cosf(a.x * b.x);
        acc += __cosf(a.y * b.y);
        acc += __cosf(a.z * b.z);
        acc += __cosf(a.w * b.w);
    }

    // Scalar tail (n_total not multiple of 4)
    long long ti = n4 * 4 + tid;
    if (ti < n_total) {
        acc += __cosf(phi[ti] * w[ti]);
    }

    // Warp reduce
    #pragma unroll
    for (int o = 16; o > 0; o >>= 1)
        acc += __shfl_xor_sync(0xffffffffu, acc, o);

    __shared__ float smem[NTHREADS / 32];
    if ((threadIdx.x & 31) == 0)
        smem[threadIdx.x >> 5] = acc;
    __syncthreads();

    // Block partial -> global, then last block finishes (fused final pass)
    __shared__ bool s_is_last;
    if (threadIdx.x == 0) {
        float v = 0.0f;
        #pragma unroll
        for (int k = 0; k < NTHREADS / 32; k++)
            v += smem[k];
        g_partials[blockIdx.x] = v;
        __threadfence();
        // atomicInc wraps to 0 when old == NBLOCKS-1 -> ready for next replay
        unsigned int ticket = atomicInc(&g_counter, NBLOCKS - 1);
        s_is_last = (ticket == NBLOCKS - 1);
    }
    __syncthreads();

    if (s_is_last) {
        // Deterministic final reduction: fixed strided assignment + fixed tree
        float v = 0.0f;
        for (int k = threadIdx.x; k < NBLOCKS; k += NTHREADS)
            v += g_partials[k];

        #pragma unroll
        for (int o = 16; o > 0; o >>= 1)
            v += __shfl_xor_sync(0xffffffffu, v, o);

        if ((threadIdx.x & 31) == 0)
            smem[threadIdx.x >> 5] = v;
        __syncthreads();

        if (threadIdx.x < 32) {
            float t = (threadIdx.x < NTHREADS / 32) ? smem[threadIdx.x] : 0.0f;
            #pragma unroll
            for (int o = 4; o > 0; o >>= 1)
                t += __shfl_xor_sync(0xffffffffu, t, o);
            if (threadIdx.x == 0)
                out[0] = (t + bias) * inv_N;
        }
    }
}

extern "C" void kernel_launch(void* const* d_in, const int* in_sizes, int n_in,
                              void* d_out, int out_size) {
    const float* phi = (const float*)d_in[0];
    const float* w   = (const float*)d_in[1];

    long long C = (long long)in_sizes[0];

    // N = 2^ceil(log2(C))
    int n = 0;
    while ((1LL << n) < C) n++;
    long long N = 1LL << n;

    float bias  = (float)(double)(N - C);
    float inv_N = (float)(1.0 / (double)N);

    long long n4 = C / 4;

    qsum_fused_kernel<<<NBLOCKS, NTHREADS>>>(phi, w, n4, C, bias, inv_N,
                                             (float*)d_out);
}